// round 13
// baseline (speedup 1.0000x reference)
#include <cuda_runtime.h>

#define BB 256
#define TT 2048
#define PP 64

typedef unsigned long long ull;

// ---------------- device scratch (static, allowed) ----------------
__device__ ull   g_E[32][64];               // g_E[k][c] = pack2(exp(A[2k][c]), exp(A[2k+1][c]))
__device__ float g_logZ[BB];
__device__ float g_nll[BB];
__device__ int   g_lab64;                   // 1 if labels are int64, 0 if int32

// ---------------- f32x2 helpers (sm_103a packed fp32) ----------------
__device__ __forceinline__ ull pack2(float lo, float hi) {
    ull r; asm("mov.b64 %0, {%1,%2};" : "=l"(r) : "f"(lo), "f"(hi)); return r;
}
__device__ __forceinline__ void unpack2(ull v, float& lo, float& hi) {
    asm("mov.b64 {%0,%1}, %2;" : "=f"(lo), "=f"(hi) : "l"(v));
}
__device__ __forceinline__ ull ffma2(ull a, ull b, ull c) {
    ull d; asm("fma.rn.f32x2 %0, %1, %2, %3;" : "=l"(d) : "l"(a), "l"(b), "l"(c)); return d;
}
__device__ __forceinline__ ull fadd2(ull a, ull b) {
    ull d; asm("add.rn.f32x2 %0, %1, %2;" : "=l"(d) : "l"(a), "l"(b)); return d;
}

// ---------------- cp.async helpers ----------------
__device__ __forceinline__ void cp_async4(void* smem, const void* gmem) {
    unsigned s = (unsigned)__cvta_generic_to_shared(smem);
    asm volatile("cp.async.ca.shared.global [%0], [%1], 4;" :: "r"(s), "l"(gmem) : "memory");
}
__device__ __forceinline__ void cp_commit() {
    asm volatile("cp.async.commit_group;" ::: "memory");
}
__device__ __forceinline__ void cp_wait6() {
    asm volatile("cp.async.wait_group 6;" ::: "memory");
}

// ---------------- kernel A0: detect labels dtype ----------------
// Reads only the first TT int32 words (in-bounds under both interpretations).
// int64 labels in [0,64) => every odd 32-bit word is zero.
__global__ void detect_kernel(const int* __restrict__ labels_raw) {
    __shared__ int nz;
    if (threadIdx.x == 0) nz = 0;
    __syncthreads();
    int acc = 0;
    for (int i = threadIdx.x; i < TT / 2; i += blockDim.x)
        acc |= labels_raw[2 * i + 1];
    if (acc) atomicOr(&nz, 1);
    __syncthreads();
    if (threadIdx.x == 0) g_lab64 = (nz == 0) ? 1 : 0;
}

// ---------------- kernel A: precompute E = exp(A), column-packed ----------------
// A in [-0.01, 0.01] => E in [0.99, 1.01]; no stabilization needed.
__global__ void precompute_kernel(const float* __restrict__ A) {
    int c = threadIdx.x;  // 0..63 output column
    for (int k = 0; k < 32; k++) {
        float elo = __expf(A[(2 * k) * PP + c]);
        float ehi = __expf(A[(2 * k + 1) * PP + c]);
        g_E[k][c] = pack2(elo, ehi);
    }
}

// ---------------- kernel B: forward recursion, 2 batches interleaved ----------------
// 64-thread CTA advances TWO independent batches per iteration; one output
// column per thread (32 FFMA2 per batch). The two dependency chains are
// independent, so their latencies hide under each other's issue; E registers
// are shared between the batches. One __syncthreads per iteration covers
// both steps. Linear recursion q_t = (E^T q_{t-1}) .* (exp(u_t) * 2^-e_t),
// e_t = exponent field of q[0] (broadcast read, exact pow-2 renorm).
__global__ __launch_bounds__(64, 1) void forward_kernel(const float* __restrict__ unary) {
    const int l = threadIdx.x;                 // owned output column 0..63
    const int bA = blockIdx.x * 2;
    const int bB = bA + 1;
    const float* UA = unary + (size_t)bA * TT * PP;
    const float* UB = unary + (size_t)bB * TT * PP;

    // transition matrix column l in registers (64 regs), shared by both batches
    ull Er[32];
#pragma unroll
    for (int k = 0; k < 32; k++) Er[k] = g_E[k][l];

    __shared__ __align__(16) float qsA[2][64], qsB[2][64];  // double-buffered q
    __shared__ float usA[8][64], usB[8][64];                // unary prefetch rings

    // prologue: prefetch u for t=1..7 for both batches, one commit group per t
#pragma unroll
    for (int t = 1; t <= 7; ++t) {
        cp_async4(&usA[t & 7][l], UA + (size_t)t * PP + l);
        cp_async4(&usB[t & 7][l], UB + (size_t)t * PP + l);
        cp_commit();
    }

    // t = 0 init
    float qA = __expf(UA[l]);
    float qB = __expf(UB[l]);
    int eA = 0, eB = 0;
    qsA[0][l] = qA;
    qsB[0][l] = qB;
    __syncthreads();

    for (int t = 1; t < TT; ++t) {
        cp_wait6();                            // ring slot t&7 ready (self-fetched)
        float uA = usA[t & 7][l];
        float uB = usB[t & 7][l];

        // refill ring 7 steps ahead (both batches, one commit group)
        int tp = t + 7;
        if (tp < TT) {
            cp_async4(&usA[tp & 7][l], UA + (size_t)tp * PP + l);
            cp_async4(&usB[tp & 7][l], UB + (size_t)tp * PP + l);
        }
        cp_commit();

        const float* pinA = qsA[(t + 1) & 1];
        const float* pinB = qsB[(t + 1) & 1];

        // renorm sources: exponent of q[0] (broadcast LDS, off the matvec path)
        unsigned qa0 = __float_as_uint(pinA[0]);
        int efA = (int)(qa0 >> 23);
        float scA = __int_as_float((254 - efA) << 23);   // exact 2^-(efA-127)
        eA += efA - 127;
        float wA = __expf(uA) * scA;

        unsigned qb0 = __float_as_uint(pinB[0]);
        int efB = (int)(qb0 >> 23);
        float scB = __int_as_float((254 - efB) << 23);
        eB += efB - 127;
        float wB = __expf(uB) * scB;

        // two independent matvecs: s_l = sum_i q_i * E[i][l]; 32 FFMA2 each,
        // 4 accumulators each; chains interleave in the issue stream
        ull a0 = 0ull, a1 = 0ull, a2 = 0ull, a3 = 0ull;
        ull c0 = 0ull, c1 = 0ull, c2 = 0ull, c3 = 0ull;
#pragma unroll
        for (int m = 0; m < 16; m += 2) {
            ulonglong2 pA0 = *(const ulonglong2*)&pinA[4 * m];
            ulonglong2 pB0 = *(const ulonglong2*)&pinB[4 * m];
            a0 = ffma2(pA0.x, Er[2 * m],     a0);
            a1 = ffma2(pA0.y, Er[2 * m + 1], a1);
            c0 = ffma2(pB0.x, Er[2 * m],     c0);
            c1 = ffma2(pB0.y, Er[2 * m + 1], c1);
            ulonglong2 pA1 = *(const ulonglong2*)&pinA[4 * m + 4];
            ulonglong2 pB1 = *(const ulonglong2*)&pinB[4 * m + 4];
            a2 = ffma2(pA1.x, Er[2 * m + 2], a2);
            a3 = ffma2(pA1.y, Er[2 * m + 3], a3);
            c2 = ffma2(pB1.x, Er[2 * m + 2], c2);
            c3 = ffma2(pB1.y, Er[2 * m + 3], c3);
        }
        ull sA = fadd2(fadd2(a0, a1), fadd2(a2, a3));
        ull sB = fadd2(fadd2(c0, c1), fadd2(c2, c3));
        float la, ha, lb, hb;
        unpack2(sA, la, ha);
        unpack2(sB, lb, hb);
        qA = (la + ha) * wA;
        qB = (lb + hb) * wB;

        qsA[t & 1][l] = qA;
        qsB[t & 1][l] = qB;
        __syncthreads();
    }

    // logZ = ln2 * eacc + log(sum over 64 columns), per batch
    __shared__ float part[4];
    const int w = l >> 5, lane = l & 31;
    float s = qA;
#pragma unroll
    for (int o = 16; o; o >>= 1) s += __shfl_xor_sync(0xffffffffu, s, o);
    if (lane == 0) part[w] = s;
    float s2 = qB;
#pragma unroll
    for (int o = 16; o; o >>= 1) s2 += __shfl_xor_sync(0xffffffffu, s2, o);
    if (lane == 0) part[2 + w] = s2;
    __syncthreads();
    if (l == 0) {
        double logZA = (double)eA * 0.6931471805599453 + log((double)(part[0] + part[1]));
        double logZB = (double)eB * 0.6931471805599453 + log((double)(part[2] + part[3]));
        g_logZ[bA] = (float)logZA;
        g_logZ[bB] = (float)logZB;
    }
}

// ---------------- kernel C: emit + transition scores (dtype-robust) ----------------
__global__ void score_kernel(const float* __restrict__ unary,
                             const void* __restrict__ labels,
                             const float* __restrict__ A) {
    const int b = blockIdx.x;
    const float* u = unary + (size_t)b * TT * PP;
    const int lab64 = g_lab64;
    double acc = 0.0;
    if (lab64) {
        const long long* lb = (const long long*)labels + (size_t)b * TT;
        for (int t = threadIdx.x; t < TT; t += blockDim.x) {
            int y = (int)lb[t];
            float v = u[(size_t)t * PP + y];
            float tr = (t > 0) ? A[((int)lb[t - 1]) * PP + y] : 0.0f;
            acc += (double)(v + tr);
        }
    } else {
        const int* lb = (const int*)labels + (size_t)b * TT;
        for (int t = threadIdx.x; t < TT; t += blockDim.x) {
            int y = lb[t];
            float v = u[(size_t)t * PP + y];
            float tr = (t > 0) ? A[lb[t - 1] * PP + y] : 0.0f;
            acc += (double)(v + tr);
        }
    }
    __shared__ double sh[256];
    sh[threadIdx.x] = acc;
    __syncthreads();
    for (int s = 128; s > 0; s >>= 1) {
        if (threadIdx.x < s) sh[threadIdx.x] += sh[threadIdx.x + s];
        __syncthreads();
    }
    if (threadIdx.x == 0) g_nll[b] = g_logZ[b] - (float)sh[0];
}

// ---------------- kernel D: deterministic mean ----------------
__global__ void final_kernel(float* out) {
    __shared__ float sh[BB];
    sh[threadIdx.x] = g_nll[threadIdx.x];
    __syncthreads();
    for (int s = 128; s > 0; s >>= 1) {
        if (threadIdx.x < s) sh[threadIdx.x] += sh[threadIdx.x + s];
        __syncthreads();
    }
    if (threadIdx.x == 0) out[0] = sh[0] / (float)BB;
}

// ---------------- launch ----------------
extern "C" void kernel_launch(void* const* d_in, const int* in_sizes, int n_in,
                              void* d_out, int out_size) {
    const float* unary = (const float*)d_in[0];
    const void* labels = d_in[1];
    const float* A = (const float*)d_in[2];

    detect_kernel<<<1, 128>>>((const int*)labels);
    precompute_kernel<<<1, 64>>>(A);
    forward_kernel<<<BB / 2, 64>>>(unary);
    score_kernel<<<BB, 256>>>(unary, labels, A);
    final_kernel<<<1, BB>>>((float*)d_out);
}

// round 15
// speedup vs baseline: 1.4578x; 1.4578x over previous
#include <cuda_runtime.h>

#define BB 256
#define TT 2048
#define PP 64

typedef unsigned long long ull;

// ---------------- device scratch (static, allowed) ----------------
__device__ ull   g_E[32][64];               // g_E[k][c] = pack2(exp(A[2k][c]), exp(A[2k+1][c]))
__device__ float g_logZ[BB];
__device__ float g_nll[BB];
__device__ int   g_lab64;                   // 1 if labels are int64, 0 if int32

// ---------------- f32x2 helpers (sm_103a packed fp32) ----------------
__device__ __forceinline__ ull pack2(float lo, float hi) {
    ull r; asm("mov.b64 %0, {%1,%2};" : "=l"(r) : "f"(lo), "f"(hi)); return r;
}
__device__ __forceinline__ void unpack2(ull v, float& lo, float& hi) {
    asm("mov.b64 {%0,%1}, %2;" : "=f"(lo), "=f"(hi) : "l"(v));
}
__device__ __forceinline__ ull ffma2(ull a, ull b, ull c) {
    ull d; asm("fma.rn.f32x2 %0, %1, %2, %3;" : "=l"(d) : "l"(a), "l"(b), "l"(c)); return d;
}
__device__ __forceinline__ ull fadd2(ull a, ull b) {
    ull d; asm("add.rn.f32x2 %0, %1, %2;" : "=l"(d) : "l"(a), "l"(b)); return d;
}

// ---------------- cp.async helpers ----------------
__device__ __forceinline__ void cp_async4(void* smem, const void* gmem) {
    unsigned s = (unsigned)__cvta_generic_to_shared(smem);
    asm volatile("cp.async.ca.shared.global [%0], [%1], 4;" :: "r"(s), "l"(gmem) : "memory");
}
__device__ __forceinline__ void cp_commit() {
    asm volatile("cp.async.commit_group;" ::: "memory");
}
__device__ __forceinline__ void cp_wait6() {
    asm volatile("cp.async.wait_group 6;" ::: "memory");
}

// ---------------- kernel A0: detect labels dtype ----------------
// Reads only the first TT int32 words (in-bounds under both interpretations).
// int64 labels in [0,64) => every odd 32-bit word is zero.
__global__ void detect_kernel(const int* __restrict__ labels_raw) {
    __shared__ int nz;
    if (threadIdx.x == 0) nz = 0;
    __syncthreads();
    int acc = 0;
    for (int i = threadIdx.x; i < TT / 2; i += blockDim.x)
        acc |= labels_raw[2 * i + 1];
    if (acc) atomicOr(&nz, 1);
    __syncthreads();
    if (threadIdx.x == 0) g_lab64 = (nz == 0) ? 1 : 0;
}

// ---------------- kernel A: precompute E = exp(A), column-packed ----------------
// A in [-0.01, 0.01] => E in [0.99, 1.01]; no stabilization needed.
__global__ void precompute_kernel(const float* __restrict__ A) {
    int c = threadIdx.x;  // 0..63 output column
    for (int k = 0; k < 32; k++) {
        float elo = __expf(A[(2 * k) * PP + c]);
        float ehi = __expf(A[(2 * k + 1) * PP + c]);
        g_E[k][c] = pack2(elo, ehi);
    }
}

// ---------------- kernel B: forward recursion (R8 dataflow + trims) ----------------
// 2 batches per 128-thread CTA; each batch on 2 warps (64 threads), one output
// column per thread (32 FFMA2). Per step: front-batched LDS.128 of the q
// broadcast vector, FFMA2 stream, exact pow-2 renorm from q[0]'s exponent
// (register reuse), STS, then post-chain ring refill, then barrier.
__global__ __launch_bounds__(128, 1) void forward_kernel(const float* __restrict__ unary) {
    const int tid = threadIdx.x;
    const int g = tid >> 6;                   // batch slot in CTA (0 or 1)
    const int l = tid & 63;                   // owned output column
    const int b = blockIdx.x * 2 + g;
    const float* Ub = unary + (size_t)b * TT * PP;

    // transition matrix column l in registers (64 regs)
    ull Er[32];
#pragma unroll
    for (int k = 0; k < 32; k++) Er[k] = g_E[k][l];

    __shared__ __align__(16) float qs[2][2][64];   // per-batch double-buffered q
    __shared__ float us[2][8][64];                 // per-batch unary prefetch ring

    // prologue: prefetch u for t=1..7, one commit group each
#pragma unroll
    for (int t = 1; t <= 7; ++t) {
        cp_async4(&us[g][t & 7][l], Ub + (size_t)t * PP + l);
        cp_commit();
    }

    // t = 0 init: q = exp(u0)
    float q = __expf(Ub[l]);
    int eacc = 0;
    qs[g][0][l] = q;
    __syncthreads();

    // one step: pin -> pout, consuming ring slot (t&7), refilling for t+7
#define STEP(T, PIN, POUT)                                                     \
    {                                                                          \
        cp_wait6();                                                            \
        float u = us[g][(T) & 7][l];                                           \
        /* front-batched broadcast loads: 16 x LDS.128 */                      \
        ulonglong2 P[16];                                                      \
        _Pragma("unroll")                                                      \
        for (int m = 0; m < 16; m++)                                           \
            P[m] = *(const ulonglong2*)&(PIN)[4 * m];                          \
        /* renorm source: exponent of q[0] from the already-loaded register */ \
        unsigned q0bits = (unsigned)P[0].x;                                    \
        int ef = (int)(q0bits >> 23);                                          \
        float sc = __int_as_float((254 - ef) << 23);                           \
        eacc += ef - 127;                                                      \
        float wgt = __expf(u) * sc;                                            \
        /* matvec: 32 FFMA2, 8 accumulators */                                 \
        ull a[8];                                                              \
        _Pragma("unroll")                                                      \
        for (int i = 0; i < 8; i++) a[i] = 0ull;                               \
        _Pragma("unroll")                                                      \
        for (int m = 0; m < 16; m++) {                                         \
            a[2 * (m & 3)]     = ffma2(P[m].x, Er[2 * m],     a[2 * (m & 3)]); \
            a[2 * (m & 3) + 1] = ffma2(P[m].y, Er[2 * m + 1], a[2 * (m & 3) + 1]); \
        }                                                                      \
        ull s01 = fadd2(fadd2(a[0], a[1]), fadd2(a[2], a[3]));                 \
        ull s23 = fadd2(fadd2(a[4], a[5]), fadd2(a[6], a[7]));                 \
        ull sp  = fadd2(s01, s23);                                             \
        float lo, hi;                                                          \
        unpack2(sp, lo, hi);                                                   \
        q = (lo + hi) * wgt;                                                   \
        (POUT)[l] = q;                                                         \
        /* post-chain ring refill for t+7 */                                   \
        int tp = (T) + 7;                                                      \
        if (tp < TT) cp_async4(&us[g][tp & 7][l], Ub + (size_t)tp * PP + l);   \
        cp_commit();                                                           \
        __syncthreads();                                                       \
    }

    // peel t = 1 (qs[0] -> qs[1]), then 1023 ping-pong pairs covering 2..2047
    STEP(1, qs[g][0], qs[g][1])
    for (int t = 2; t < TT; t += 2) {
        STEP(t,     qs[g][1], qs[g][0])
        STEP(t + 1, qs[g][0], qs[g][1])
    }
#undef STEP

    // logZ = ln2 * eacc + log(sum over 64 columns)
    __shared__ float part[2][4];
    const int w4 = (tid >> 5) & 1, lane = tid & 31;
    float s = q;
#pragma unroll
    for (int o = 16; o; o >>= 1) s += __shfl_xor_sync(0xffffffffu, s, o);
    if (lane == 0) part[g][w4] = s;
    __syncthreads();
    if (l == 0) {
        float tot = part[g][0] + part[g][1];
        double logZ = (double)eacc * 0.6931471805599453 + log((double)tot);
        g_logZ[b] = (float)logZ;
    }
}

// ---------------- kernel C: emit + transition scores (dtype-robust) ----------------
__global__ void score_kernel(const float* __restrict__ unary,
                             const void* __restrict__ labels,
                             const float* __restrict__ A) {
    const int b = blockIdx.x;
    const float* u = unary + (size_t)b * TT * PP;
    const int lab64 = g_lab64;
    double acc = 0.0;
    if (lab64) {
        const long long* lb = (const long long*)labels + (size_t)b * TT;
        for (int t = threadIdx.x; t < TT; t += blockDim.x) {
            int y = (int)lb[t];
            float v = u[(size_t)t * PP + y];
            float tr = (t > 0) ? A[((int)lb[t - 1]) * PP + y] : 0.0f;
            acc += (double)(v + tr);
        }
    } else {
        const int* lb = (const int*)labels + (size_t)b * TT;
        for (int t = threadIdx.x; t < TT; t += blockDim.x) {
            int y = lb[t];
            float v = u[(size_t)t * PP + y];
            float tr = (t > 0) ? A[lb[t - 1] * PP + y] : 0.0f;
            acc += (double)(v + tr);
        }
    }
    __shared__ double sh[256];
    sh[threadIdx.x] = acc;
    __syncthreads();
    for (int s = 128; s > 0; s >>= 1) {
        if (threadIdx.x < s) sh[threadIdx.x] += sh[threadIdx.x + s];
        __syncthreads();
    }
    if (threadIdx.x == 0) g_nll[b] = g_logZ[b] - (float)sh[0];
}

// ---------------- kernel D: deterministic mean ----------------
__global__ void final_kernel(float* out) {
    __shared__ float sh[BB];
    sh[threadIdx.x] = g_nll[threadIdx.x];
    __syncthreads();
    for (int s = 128; s > 0; s >>= 1) {
        if (threadIdx.x < s) sh[threadIdx.x] += sh[threadIdx.x + s];
        __syncthreads();
    }
    if (threadIdx.x == 0) out[0] = sh[0] / (float)BB;
}

// ---------------- launch ----------------
extern "C" void kernel_launch(void* const* d_in, const int* in_sizes, int n_in,
                              void* d_out, int out_size) {
    const float* unary = (const float*)d_in[0];
    const void* labels = d_in[1];
    const float* A = (const float*)d_in[2];

    detect_kernel<<<1, 128>>>((const int*)labels);
    precompute_kernel<<<1, 64>>>(A);
    forward_kernel<<<BB / 2, 128>>>(unary);
    score_kernel<<<BB, 256>>>(unary, labels, A);
    final_kernel<<<1, BB>>>((float*)d_out);
}